// round 10
// baseline (speedup 1.0000x reference)
#include <cuda_runtime.h>
#include <cuda_fp16.h>
#include <stdint.h>

#define Q_N   4096
#define D_N   32768
#define DIM   128
#define TQ    128
#define TN    128
#define LDSKB 144                    // padded smem row stride in BYTES (9 x 16B, odd -> conflict-free)
#define NSLICE 32
#define SUBS  ((D_N / TN) / NSLICE)  // 8 D-subtiles per CTA
#define TILE_B (TQ * LDSKB)          // 18432 B per 128x128 s8 tile
#define NBLK16 (D_N / 16)            // 2048 16-col blocks per row
#define MARGIN 2.25f
#define CAND_CAP 256
#define SCALE  24.0f
#define INV_S2 (1.0f / (SCALE * SCALE))

// ---- device scratch ----
__device__ __align__(16) char g_q8[Q_N * DIM];
__device__ __align__(16) char g_d8[D_N * DIM];
__device__ unsigned short g_lmax16[(size_t)Q_N * NBLK16];   // 16 MB, f16 bits
__device__ uint32_t g_cands[(size_t)Q_N * CAND_CAP];
__device__ int      g_ccount;
__device__ unsigned long long g_key[Q_N];

// ---- helpers ----
__device__ __forceinline__ uint32_t smem_u32(const void* p) {
    uint32_t a;
    asm("{ .reg .u64 t; cvta.to.shared.u64 t, %1; cvt.u32.u64 %0, t; }" : "=r"(a) : "l"(p));
    return a;
}
__device__ __forceinline__ void cpa16(void* s, const void* g) {
    unsigned sa = smem_u32(s);
    asm volatile("cp.async.cg.shared.global [%0], [%1], 16;" :: "r"(sa), "l"(g));
}
#define CP_COMMIT() asm volatile("cp.async.commit_group;" ::: "memory")
#define CP_WAIT0()  asm volatile("cp.async.wait_group 0;" ::: "memory")

// load a [128 x 128] s8 tile (gmem row stride DIM bytes) into smem rows of stride LDSKB
__device__ __forceinline__ void load_tile(char* dst, const char* gsrc, int tid) {
#pragma unroll
    for (int t = 0; t < 4; t++) {
        int chunk = tid + t * 256;      // 1024 16B chunks
        int row = chunk >> 3;
        int c   = chunk & 7;
        cpa16(dst + row * LDSKB + c * 16, gsrc + row * DIM + c * 16);
    }
}
__device__ __forceinline__ void ldm_x4(uint32_t* r, uint32_t addr) {
    asm volatile("ldmatrix.sync.aligned.m8n8.x4.shared.b16 {%0,%1,%2,%3}, [%4];"
        : "=r"(r[0]), "=r"(r[1]), "=r"(r[2]), "=r"(r[3]) : "r"(addr));
}
// s8 x s8 -> s32 accum mma, K=32
__device__ __forceinline__ void mma_s8(int* c, const uint32_t* a, uint32_t b0, uint32_t b1) {
    asm volatile(
        "mma.sync.aligned.m16n8k32.row.col.s32.s8.s8.s32 "
        "{%0,%1,%2,%3}, {%4,%5,%6,%7}, {%8,%9}, {%0,%1,%2,%3};\n"
        : "+r"(c[0]), "+r"(c[1]), "+r"(c[2]), "+r"(c[3])
        : "r"(a[0]), "r"(a[1]), "r"(a[2]), "r"(a[3]), "r"(b0), "r"(b1));
}
__device__ __forceinline__ unsigned long long pack_key(float v, unsigned col) {
    unsigned u = __float_as_uint(v);
    u = (u & 0x80000000u) ? ~u : (u | 0x80000000u);
    return ((unsigned long long)u << 32) | (unsigned long long)(0xFFFFFFFFu - col);
}
__device__ __forceinline__ float bits_f16(unsigned short u) {
    __half h = *reinterpret_cast<__half*>(&u);
    return __half2float(h);
}
__device__ __forceinline__ uint32_t quant4(float4 v) {
    int a = __float2int_rn(fminf(fmaxf(v.x * SCALE, -127.f), 127.f));
    int b = __float2int_rn(fminf(fmaxf(v.y * SCALE, -127.f), 127.f));
    int c = __float2int_rn(fminf(fmaxf(v.z * SCALE, -127.f), 127.f));
    int d = __float2int_rn(fminf(fmaxf(v.w * SCALE, -127.f), 127.f));
    return (uint32_t)(a & 0xFF) | ((uint32_t)(b & 0xFF) << 8) |
           ((uint32_t)(c & 0xFF) << 16) | ((uint32_t)(d & 0xFF) << 24);
}

// =====================================================================
// Pass 0: fp32 -> s8 (scale 24, clamp +-127); reset keys + counter
// =====================================================================
__global__ void convert_kernel(const float4* __restrict__ qe, const float4* __restrict__ de) {
    const int i = blockIdx.x * blockDim.x + threadIdx.x;   // 0 .. D_N*DIM/8-1
#pragma unroll
    for (int r = 0; r < 2; r++) {
        int j = i + r * (D_N * DIM / 8);
        ((uint32_t*)g_d8)[j] = quant4(de[j]);
    }
    if (i < Q_N * DIM / 4) ((uint32_t*)g_q8)[i] = quant4(qe[i]);
    if (i < Q_N) g_key[i] = 0ull;
    if (i == 0)  g_ccount = 0;
}

// =====================================================================
// Pass 1: s8 IMMA GEMM (s32 accum), A register-resident,
//         per-(row, 16-col block) f16 max table
// =====================================================================
__global__ __launch_bounds__(256, 2) void approx_kernel() {
    extern __shared__ char sm[];
    char* As    = sm;                  // [128 x LDSKB]
    char* Bbase = As + TILE_B;         // 2 x [128 x LDSKB]

    const int tid  = threadIdx.x;
    const int wid  = tid >> 5;
    const int lane = tid & 31;
    const int g    = lane >> 2;
    const int qr   = lane & 3;
    const int wid_m = wid >> 1;
    const int wid_n = wid & 1;
    const int qtile = blockIdx.x;
    const int d0    = blockIdx.y * (SUBS * TN);

    // prologue: A tile + B0 tile
    load_tile(As, g_q8 + (size_t)qtile * TQ * DIM, tid);
    load_tile(Bbase, g_d8 + (size_t)d0 * DIM, tid);
    CP_COMMIT();

    const int rowA  = wid_m * 32 + (lane & 15);
    const int colAb = ((lane >> 4) & 1) * 16;          // 16B k-half within k32 step
    const uint32_t aBase = smem_u32(As) + rowA * LDSKB + colAb;
    const int rowB  = wid_n * 64 + (lane & 7) + ((lane >> 4) << 3);
    const int colBb = ((lane >> 3) & 1) * 16;
    const uint32_t b_lane_off = (uint32_t)(rowB * LDSKB + colBb);
    const uint32_t b_smem0 = smem_u32(Bbase);

    const int row0 = qtile * TQ + wid_m * 32 + g;

    CP_WAIT0();
    __syncthreads();

    // A fragments resident: 2 m-tiles x 4 k32-steps x 4 regs = 32 regs
    uint32_t aF[2][4][4];
#pragma unroll
    for (int ks = 0; ks < 4; ks++) {
        ldm_x4(aF[0][ks], aBase + (uint32_t)(ks * 32));
        ldm_x4(aF[1][ks], aBase + 16 * LDSKB + (uint32_t)(ks * 32));
    }

    for (int s = 0; s < SUBS; s++) {
        if (s > 0) { CP_WAIT0(); __syncthreads(); }
        if (s + 1 < SUBS) {
            load_tile(Bbase + ((s + 1) & 1) * TILE_B, g_d8 + (size_t)(d0 + (s + 1) * TN) * DIM, tid);
            CP_COMMIT();
        }
        const uint32_t bB = b_smem0 + (uint32_t)(s & 1) * TILE_B + b_lane_off;   // FIXED: bytes, not 2x

        int acc[2][8][4];
#pragma unroll
        for (int mt = 0; mt < 2; mt++)
#pragma unroll
            for (int nt = 0; nt < 8; nt++)
#pragma unroll
                for (int i = 0; i < 4; i++) acc[mt][nt][i] = 0;

#pragma unroll
        for (int ks = 0; ks < 4; ks++) {
            const uint32_t ko = (uint32_t)(ks * 32);
            uint32_t bF[4][4];
#pragma unroll
            for (int p = 0; p < 4; p++)
                ldm_x4(bF[p], bB + (uint32_t)(p * 16 * LDSKB) + ko);
#pragma unroll
            for (int mt = 0; mt < 2; mt++)
#pragma unroll
                for (int p = 0; p < 4; p++) {
                    mma_s8(acc[mt][2 * p],     aF[mt][ks], bF[p][0], bF[p][1]);
                    mma_s8(acc[mt][2 * p + 1], aF[mt][ks], bF[p][2], bF[p][3]);
                }
        }

        // per (row-slot, 16-col block) max, int domain; quad-rank reduce
        const int gblk = (blockIdx.y * SUBS + s) * 8 + wid_n * 4;
#pragma unroll
        for (int sl = 0; sl < 4; sl++) {
            const int mt = sl >> 1;
            const int r0 = (sl & 1) * 2;                 // regs {0,1} or {2,3}
            unsigned short outv[4];
#pragma unroll
            for (int b = 0; b < 4; b++) {
                int m = max(max(acc[mt][2 * b][r0], acc[mt][2 * b][r0 + 1]),
                            max(acc[mt][2 * b + 1][r0], acc[mt][2 * b + 1][r0 + 1]));
#pragma unroll
                for (int off = 1; off < 4; off <<= 1)
                    m = max(m, __shfl_xor_sync(0xffffffffu, m, off));
                __half hv = __float2half_rn((float)m * INV_S2);
                outv[b] = *reinterpret_cast<unsigned short*>(&hv);
            }
            if (qr == 0) {
                ushort4 v; v.x = outv[0]; v.y = outv[1]; v.z = outv[2]; v.w = outv[3];
                *(ushort4*)(g_lmax16 + (size_t)(row0 + sl * 8) * NBLK16 + gblk) = v;
            }
        }
    }
}

// =====================================================================
// Pass 2: single-pass per-row scan (values stay in registers)
// =====================================================================
__global__ void scan_kernel() {
    const int row = blockIdx.x;
    const int t   = threadIdx.x;     // 256 threads, 8 blocks each
    __shared__ float red[256];
    __shared__ int lcnt, base;
    __shared__ uint32_t lbuf[CAND_CAP];

    uint4 raw = ((const uint4*)(g_lmax16 + (size_t)row * NBLK16))[t];
    float v[8];
    v[0] = bits_f16((unsigned short)(raw.x & 0xFFFF));
    v[1] = bits_f16((unsigned short)(raw.x >> 16));
    v[2] = bits_f16((unsigned short)(raw.y & 0xFFFF));
    v[3] = bits_f16((unsigned short)(raw.y >> 16));
    v[4] = bits_f16((unsigned short)(raw.z & 0xFFFF));
    v[5] = bits_f16((unsigned short)(raw.z >> 16));
    v[6] = bits_f16((unsigned short)(raw.w & 0xFFFF));
    v[7] = bits_f16((unsigned short)(raw.w >> 16));

    float m = v[0];
#pragma unroll
    for (int j = 1; j < 8; j++) m = fmaxf(m, v[j]);
    red[t] = m;
    __syncthreads();
    for (int off = 128; off > 0; off >>= 1) {
        if (t < off) red[t] = fmaxf(red[t], red[t + off]);
        __syncthreads();
    }
    const float thr = red[0] - MARGIN;
    if (t == 0) lcnt = 0;
    __syncthreads();

#pragma unroll
    for (int j = 0; j < 8; j++) {
        if (v[j] >= thr) {
            int p = atomicAdd(&lcnt, 1);
            if (p < CAND_CAP) lbuf[p] = ((uint32_t)row << 11) | (uint32_t)(t * 8 + j);
        }
    }
    __syncthreads();
    int cnt = lcnt < CAND_CAP ? lcnt : CAND_CAP;
    if (t == 0) base = atomicAdd(&g_ccount, cnt);
    __syncthreads();
    for (int j = t; j < cnt; j += 256) g_cands[base + j] = lbuf[j];
}

// =====================================================================
// Pass 3: exact fp32 recompute; 1 warp/candidate, coalesced row loads
// =====================================================================
__global__ void __launch_bounds__(128) exact_kernel(const float* __restrict__ qe,
                                                    const float* __restrict__ de) {
    const int warp  = (blockIdx.x * blockDim.x + threadIdx.x) >> 5;
    const int lane  = threadIdx.x & 31;
    const int nwarp = (gridDim.x * blockDim.x) >> 5;
    const int n     = g_ccount;
    const bool hi   = (lane >= 16);

    for (int e = warp; e < n; e += nwarp) {
        const uint32_t ent = g_cands[e];
        const int row  = (int)(ent >> 11);
        const int col0 = (int)(ent & 2047u) * 16;

        const float4 q4 = ((const float4*)(qe + (size_t)row * DIM))[lane];

        float p[16];
#pragma unroll
        for (int b = 0; b < 2; b++) {
            float4 d[8];
#pragma unroll
            for (int r = 0; r < 8; r++)
                d[r] = ((const float4*)(de + (size_t)(col0 + b * 8 + r) * DIM))[lane];
#pragma unroll
            for (int r = 0; r < 8; r++)
                p[b * 8 + r] = fmaf(q4.x, d[r].x, fmaf(q4.y, d[r].y, fmaf(q4.z, d[r].z, q4.w * d[r].w)));
        }

        float y[8];
#pragma unroll
        for (int j = 0; j < 8; j++) {
            float a = hi ? p[j + 8] : p[j];
            float b = hi ? p[j] : p[j + 8];
            y[j] = a + __shfl_xor_sync(0xffffffffu, b, 16);
        }
#pragma unroll
        for (int off = 1; off < 16; off <<= 1)
#pragma unroll
            for (int j = 0; j < 8; j++)
                y[j] += __shfl_xor_sync(0xffffffffu, y[j], off);

        float    s = y[0];
        unsigned c = (unsigned)(col0 + (hi ? 8 : 0));
#pragma unroll
        for (int j = 1; j < 8; j++)
            if (y[j] > s) { s = y[j]; c = (unsigned)(col0 + (hi ? 8 : 0) + j); }
        {
            float    os = __shfl_xor_sync(0xffffffffu, s, 16);
            unsigned oc = __shfl_xor_sync(0xffffffffu, c, 16);
            if (os > s || (os == s && oc < c)) { s = os; c = oc; }
        }
        if (lane == 0) atomicMax(&g_key[row], pack_key(s, c));
    }
}

// =====================================================================
// Pass 4: gather weights, normalized weighted sum
// =====================================================================
__global__ void finalize_kernel(const int* __restrict__ qids, const int* __restrict__ dids,
                                const float* __restrict__ qwt, const float* __restrict__ dwt,
                                float* __restrict__ out) {
    __shared__ float sA[256], sB[256], sC[256];
    int tid = threadIdx.x;
    float a = 0.f, b = 0.f, c = 0.f;
    for (int q = tid; q < Q_N; q += 256) {
        unsigned long long k = g_key[q];
        unsigned u    = (unsigned)(k >> 32);
        unsigned bits = (u & 0x80000000u) ? (u & 0x7FFFFFFFu) : ~u;
        float    ms   = __uint_as_float(bits);
        unsigned col  = 0xFFFFFFFFu - (unsigned)(k & 0xFFFFFFFFu);
        float comb = qwt[qids[q]] * dwt[dids[col]];
        a += comb; b += comb * ms; c += ms;
    }
    sA[tid] = a; sB[tid] = b; sC[tid] = c;
    __syncthreads();
    for (int off = 128; off > 0; off >>= 1) {
        if (tid < off) { sA[tid] += sA[tid + off]; sB[tid] += sB[tid + off]; sC[tid] += sC[tid + off]; }
        __syncthreads();
    }
    if (tid == 0) out[0] = (sA[0] > 0.f) ? (sB[0] / sA[0]) : (sC[0] / (float)Q_N);
}

// =====================================================================
// launch
// =====================================================================
extern "C" void kernel_launch(void* const* d_in, const int* in_sizes, int n_in,
                              void* d_out, int out_size) {
    const float* qe  = (const float*)d_in[0];
    const float* de  = (const float*)d_in[1];
    const int*   qid = (const int*)d_in[2];
    const int*   did = (const int*)d_in[3];
    const float* qwt = (const float*)d_in[4];
    const float* dwt = (const float*)d_in[5];
    float* out = (float*)d_out;

    size_t smem = (size_t)(3 * TILE_B);   // 55,296 B -> 2 CTAs/SM
    cudaFuncSetAttribute(approx_kernel, cudaFuncAttributeMaxDynamicSharedMemorySize, (int)smem);

    convert_kernel<<<D_N * DIM / 8 / 256, 256>>>((const float4*)qe, (const float4*)de);
    approx_kernel<<<dim3(Q_N / TQ, NSLICE), 256, smem>>>();
    scan_kernel<<<Q_N, 256>>>();
    exact_kernel<<<512, 128>>>(qe, de);
    finalize_kernel<<<1, 256>>>(qid, did, qwt, dwt, out);
}

// round 11
// speedup vs baseline: 2.0135x; 2.0135x over previous
#include <cuda_runtime.h>
#include <cuda_fp16.h>
#include <stdint.h>

#define Q_N   4096
#define D_N   32768
#define DIM   128
#define TQ    128
#define TN    128
#define LDSK  136                    // padded smem row stride in f16 elems (272 B)
#define ROWB  272
#define NSLICE 32
#define SUBS  ((D_N / TN) / NSLICE)  // 8 D-subtiles per CTA
#define TILE_E (TQ * LDSK)
#define NBLK16 (D_N / 16)            // 2048 16-col blocks per row
#define MARGIN 1.25f
#define CAND_CAP 256

// ---- device scratch ----
__device__ __half g_qh[Q_N * DIM];
__device__ __half g_dh[D_N * DIM];
__device__ unsigned short g_lmax16[(size_t)Q_N * NBLK16];   // 16 MB, f16 bits
__device__ float g_ms[Q_N];
__device__ int   g_col[Q_N];

// ---- helpers ----
__device__ __forceinline__ uint32_t smem_u32(const void* p) {
    uint32_t a;
    asm("{ .reg .u64 t; cvta.to.shared.u64 t, %1; cvt.u32.u64 %0, t; }" : "=r"(a) : "l"(p));
    return a;
}
__device__ __forceinline__ void cpa16(void* s, const void* g) {
    unsigned sa = smem_u32(s);
    asm volatile("cp.async.cg.shared.global [%0], [%1], 16;" :: "r"(sa), "l"(g));
}
#define CP_COMMIT() asm volatile("cp.async.commit_group;" ::: "memory")
#define CP_WAIT0()  asm volatile("cp.async.wait_group 0;" ::: "memory")

__device__ __forceinline__ void load_tile(__half* dst, const __half* gsrc, int tid) {
#pragma unroll
    for (int t = 0; t < 8; t++) {
        int chunk = tid + t * 256;
        int row = chunk >> 4;
        int c   = chunk & 15;
        cpa16(dst + row * LDSK + c * 8, gsrc + row * DIM + c * 8);
    }
}
__device__ __forceinline__ void ldm_x4(uint32_t* r, uint32_t addr) {
    asm volatile("ldmatrix.sync.aligned.m8n8.x4.shared.b16 {%0,%1,%2,%3}, [%4];"
        : "=r"(r[0]), "=r"(r[1]), "=r"(r[2]), "=r"(r[3]) : "r"(addr));
}
// f16 x f16 -> f16 accum mma
__device__ __forceinline__ void mma_f16(uint32_t* c, const uint32_t* a, uint32_t b0, uint32_t b1) {
    asm volatile(
        "mma.sync.aligned.m16n8k16.row.col.f16.f16.f16.f16 "
        "{%0,%1}, {%2,%3,%4,%5}, {%6,%7}, {%0,%1};\n"
        : "+r"(c[0]), "+r"(c[1])
        : "r"(a[0]), "r"(a[1]), "r"(a[2]), "r"(a[3]), "r"(b0), "r"(b1));
}
__device__ __forceinline__ float bits_f16(unsigned short u) {
    __half h = *reinterpret_cast<__half*>(&u);
    return __half2float(h);
}

// =====================================================================
// Pass 0: fp32 -> fp16
// =====================================================================
__global__ void convert_kernel(const float4* __restrict__ qe, const float4* __restrict__ de) {
    const int i = blockIdx.x * blockDim.x + threadIdx.x;   // 0 .. D_N*DIM/8-1
#pragma unroll
    for (int r = 0; r < 2; r++) {
        int j = i + r * (D_N * DIM / 8);
        float4 v = de[j];
        ((__half2*)g_dh)[2 * j]     = __floats2half2_rn(v.x, v.y);
        ((__half2*)g_dh)[2 * j + 1] = __floats2half2_rn(v.z, v.w);
    }
    if (i < Q_N * DIM / 4) {
        float4 v = qe[i];
        ((__half2*)g_qh)[2 * i]     = __floats2half2_rn(v.x, v.y);
        ((__half2*)g_qh)[2 * i + 1] = __floats2half2_rn(v.z, v.w);
    }
}

// =====================================================================
// Pass 1: f16 GEMM (f16 accum), A register-resident, B-only smem traffic,
//         per-(row, 16-col block) f16 max table   [identical to R8]
// =====================================================================
__global__ __launch_bounds__(256, 2) void approx_kernel() {
    extern __shared__ __half sm[];
    __half* As    = sm;                 // [128 x LDSK]
    __half* Bbase = As + TILE_E;        // 2 x [128 x LDSK]

    const int tid  = threadIdx.x;
    const int wid  = tid >> 5;
    const int lane = tid & 31;
    const int g    = lane >> 2;
    const int qr   = lane & 3;
    const int wid_m = wid >> 1;
    const int wid_n = wid & 1;
    const int qtile = blockIdx.x;
    const int d0    = blockIdx.y * (SUBS * TN);

    load_tile(As, g_qh + (size_t)qtile * TQ * DIM, tid);
    load_tile(Bbase, g_dh + (size_t)d0 * DIM, tid);
    CP_COMMIT();

    const int rowA  = wid_m * 32 + (lane & 15);
    const int colAb = ((lane >> 4) & 1) * 16;
    const uint32_t aBase = smem_u32(As) + rowA * ROWB + colAb;
    const int rowB  = wid_n * 64 + (lane & 7) + ((lane >> 4) << 3);
    const int colBb = ((lane >> 3) & 1) * 16;
    const uint32_t b_lane_off = (uint32_t)(rowB * ROWB + colBb);
    const uint32_t b_smem0 = smem_u32(Bbase);

    const int row0 = qtile * TQ + wid_m * 32 + g;

    CP_WAIT0();
    __syncthreads();

    uint32_t aF[2][8][4];
#pragma unroll
    for (int ks = 0; ks < 8; ks++) {
        ldm_x4(aF[0][ks], aBase + (uint32_t)(ks * 32));
        ldm_x4(aF[1][ks], aBase + 16 * ROWB + (uint32_t)(ks * 32));
    }

    for (int s = 0; s < SUBS; s++) {
        if (s > 0) { CP_WAIT0(); __syncthreads(); }
        if (s + 1 < SUBS) {
            load_tile(Bbase + ((s + 1) & 1) * TILE_E, g_dh + (size_t)(d0 + (s + 1) * TN) * DIM, tid);
            CP_COMMIT();
        }
        const uint32_t bH_base = b_smem0 + (uint32_t)(s & 1) * (TILE_E * 2) + b_lane_off;

        uint32_t acc[2][8][2];
#pragma unroll
        for (int mt = 0; mt < 2; mt++)
#pragma unroll
            for (int nt = 0; nt < 8; nt++) { acc[mt][nt][0] = 0u; acc[mt][nt][1] = 0u; }

#pragma unroll
        for (int ks = 0; ks < 8; ks++) {
            const uint32_t ko = (uint32_t)(ks * 32);
            uint32_t bH[4][4];
#pragma unroll
            for (int p = 0; p < 4; p++)
                ldm_x4(bH[p], bH_base + (uint32_t)(p * 16 * ROWB) + ko);
#pragma unroll
            for (int mt = 0; mt < 2; mt++)
#pragma unroll
                for (int p = 0; p < 4; p++) {
                    mma_f16(acc[mt][2 * p],     aF[mt][ks], bH[p][0], bH[p][1]);
                    mma_f16(acc[mt][2 * p + 1], aF[mt][ks], bH[p][2], bH[p][3]);
                }
        }

        const int gblk = (blockIdx.y * SUBS + s) * 8 + wid_n * 4;
#pragma unroll
        for (int sl = 0; sl < 4; sl++) {
            const int mt = sl >> 1, rg = sl & 1;
            unsigned short outv[4];
#pragma unroll
            for (int b = 0; b < 4; b++) {
                __half2 h0 = *reinterpret_cast<const __half2*>(&acc[mt][2 * b][rg]);
                __half2 h1 = *reinterpret_cast<const __half2*>(&acc[mt][2 * b + 1][rg]);
                __half2 hm = __hmax2(h0, h1);
                float m = fmaxf(__half2float(__low2half(hm)), __half2float(__high2half(hm)));
#pragma unroll
                for (int off = 1; off < 4; off <<= 1)
                    m = fmaxf(m, __shfl_xor_sync(0xffffffffu, m, off));
                __half hv = __float2half_rn(m);
                outv[b] = *reinterpret_cast<unsigned short*>(&hv);
            }
            if (qr == 0) {
                ushort4 v; v.x = outv[0]; v.y = outv[1]; v.z = outv[2]; v.w = outv[3];
                *(ushort4*)(g_lmax16 + (size_t)(row0 + sl * 8) * NBLK16 + gblk) = v;
            }
        }
    }
}

// =====================================================================
// Pass 2: FUSED scan + exact. One block per query row:
//   rowmax over 2048 f16 block-maxima -> threshold -> smem candidate list
//   -> warps recompute candidates in exact fp32 -> direct g_ms/g_col write
// =====================================================================
__global__ void __launch_bounds__(256) scanexact_kernel(const float* __restrict__ qe,
                                                        const float* __restrict__ de) {
    const int row = blockIdx.x;
    const int t   = threadIdx.x;
    const int wid  = t >> 5;
    const int lane = t & 31;
    const bool hi  = (lane >= 16);
    __shared__ float red[256];
    __shared__ int lcnt;
    __shared__ uint32_t lblk[CAND_CAP];
    __shared__ float    cval[CAND_CAP];
    __shared__ unsigned ccol[CAND_CAP];

    // --- scan phase ---
    uint4 raw = ((const uint4*)(g_lmax16 + (size_t)row * NBLK16))[t];
    float v[8];
    v[0] = bits_f16((unsigned short)(raw.x & 0xFFFF));
    v[1] = bits_f16((unsigned short)(raw.x >> 16));
    v[2] = bits_f16((unsigned short)(raw.y & 0xFFFF));
    v[3] = bits_f16((unsigned short)(raw.y >> 16));
    v[4] = bits_f16((unsigned short)(raw.z & 0xFFFF));
    v[5] = bits_f16((unsigned short)(raw.z >> 16));
    v[6] = bits_f16((unsigned short)(raw.w & 0xFFFF));
    v[7] = bits_f16((unsigned short)(raw.w >> 16));

    float m = v[0];
#pragma unroll
    for (int j = 1; j < 8; j++) m = fmaxf(m, v[j]);
    red[t] = m;
    if (t == 0) lcnt = 0;
    __syncthreads();
    for (int off = 128; off > 0; off >>= 1) {
        if (t < off) red[t] = fmaxf(red[t], red[t + off]);
        __syncthreads();
    }
    const float thr = red[0] - MARGIN;

#pragma unroll
    for (int j = 0; j < 8; j++) {
        if (v[j] >= thr) {
            int p = atomicAdd(&lcnt, 1);
            if (p < CAND_CAP) lblk[p] = (uint32_t)(t * 8 + j);
        }
    }
    __syncthreads();
    const int cnt = lcnt < CAND_CAP ? lcnt : CAND_CAP;

    // --- exact phase: warp e-strided over candidates ---
    const float4 q4 = ((const float4*)(qe + (size_t)row * DIM))[lane];

    for (int e = wid; e < cnt; e += 8) {
        const int col0 = (int)lblk[e] * 16;

        float p[16];
#pragma unroll
        for (int b = 0; b < 2; b++) {
            float4 d[8];
#pragma unroll
            for (int r = 0; r < 8; r++)
                d[r] = ((const float4*)(de + (size_t)(col0 + b * 8 + r) * DIM))[lane];
#pragma unroll
            for (int r = 0; r < 8; r++)
                p[b * 8 + r] = fmaf(q4.x, d[r].x, fmaf(q4.y, d[r].y, fmaf(q4.z, d[r].z, q4.w * d[r].w)));
        }

        float y[8];
#pragma unroll
        for (int j = 0; j < 8; j++) {
            float a = hi ? p[j + 8] : p[j];
            float b = hi ? p[j] : p[j + 8];
            y[j] = a + __shfl_xor_sync(0xffffffffu, b, 16);
        }
#pragma unroll
        for (int off = 1; off < 16; off <<= 1)
#pragma unroll
            for (int j = 0; j < 8; j++)
                y[j] += __shfl_xor_sync(0xffffffffu, y[j], off);

        float    s = y[0];
        unsigned c = (unsigned)(col0 + (hi ? 8 : 0));
#pragma unroll
        for (int j = 1; j < 8; j++)
            if (y[j] > s) { s = y[j]; c = (unsigned)(col0 + (hi ? 8 : 0) + j); }
        {
            float    os = __shfl_xor_sync(0xffffffffu, s, 16);
            unsigned oc = __shfl_xor_sync(0xffffffffu, c, 16);
            if (os > s || (os == s && oc < c)) { s = os; c = oc; }
        }
        if (lane == 0) { cval[e] = s; ccol[e] = c; }
    }
    __syncthreads();

    // --- final reduce over candidates (warp 0); ties -> smaller column ---
    if (t < 32) {
        float    s = -3.402823466e38f;
        unsigned c = 0xFFFFFFFFu;
        for (int e = lane; e < cnt; e += 32) {
            float    es = cval[e];
            unsigned ec = ccol[e];
            if (es > s || (es == s && ec < c)) { s = es; c = ec; }
        }
#pragma unroll
        for (int off = 1; off < 32; off <<= 1) {
            float    os = __shfl_xor_sync(0xffffffffu, s, off);
            unsigned oc = __shfl_xor_sync(0xffffffffu, c, off);
            if (os > s || (os == s && oc < c)) { s = os; c = oc; }
        }
        if (lane == 0) { g_ms[row] = s; g_col[row] = (int)c; }
    }
}

// =====================================================================
// Pass 3: gather weights, normalized weighted sum
// =====================================================================
__global__ void finalize_kernel(const int* __restrict__ qids, const int* __restrict__ dids,
                                const float* __restrict__ qwt, const float* __restrict__ dwt,
                                float* __restrict__ out) {
    __shared__ float sA[256], sB[256], sC[256];
    int tid = threadIdx.x;
    float a = 0.f, b = 0.f, c = 0.f;
    for (int q = tid; q < Q_N; q += 256) {
        float ms = g_ms[q];
        int  col = g_col[q];
        float comb = qwt[qids[q]] * dwt[dids[col]];
        a += comb; b += comb * ms; c += ms;
    }
    sA[tid] = a; sB[tid] = b; sC[tid] = c;
    __syncthreads();
    for (int off = 128; off > 0; off >>= 1) {
        if (tid < off) { sA[tid] += sA[tid + off]; sB[tid] += sB[tid + off]; sC[tid] += sC[tid + off]; }
        __syncthreads();
    }
    if (tid == 0) out[0] = (sA[0] > 0.f) ? (sB[0] / sA[0]) : (sC[0] / (float)Q_N);
}

// =====================================================================
// launch
// =====================================================================
extern "C" void kernel_launch(void* const* d_in, const int* in_sizes, int n_in,
                              void* d_out, int out_size) {
    const float* qe  = (const float*)d_in[0];
    const float* de  = (const float*)d_in[1];
    const int*   qid = (const int*)d_in[2];
    const int*   did = (const int*)d_in[3];
    const float* qwt = (const float*)d_in[4];
    const float* dwt = (const float*)d_in[5];
    float* out = (float*)d_out;

    size_t smem = (size_t)(3 * TILE_E) * sizeof(__half);   // 104,448 B -> 2 CTAs/SM
    cudaFuncSetAttribute(approx_kernel, cudaFuncAttributeMaxDynamicSharedMemorySize, (int)smem);

    convert_kernel<<<D_N * DIM / 8 / 256, 256>>>((const float4*)qe, (const float4*)de);
    approx_kernel<<<dim3(Q_N / TQ, NSLICE), 256, smem>>>();
    scanexact_kernel<<<Q_N, 256>>>(qe, de);
    finalize_kernel<<<1, 256>>>(qid, did, qwt, dwt, out);
}

// round 12
// speedup vs baseline: 2.2067x; 1.0960x over previous
#include <cuda_runtime.h>
#include <cuda_fp16.h>
#include <stdint.h>

#define Q_N   4096
#define D_N   32768
#define DIM   128
#define TQ    128
#define TN    128
#define LDSK  136                    // padded smem row stride in f16 elems (272 B)
#define ROWB  272
#define NSLICE 32
#define SUBS  ((D_N / TN) / NSLICE)  // 8 D-subtiles per CTA
#define TILE_E (TQ * LDSK)
#define NBLK16 (D_N / 16)            // 2048 16-col blocks per row
#define MARGIN 1.25f
#define CAND_CAP 256

// ---- device scratch ----
__device__ __half g_qh[Q_N * DIM];
__device__ __half g_dh[D_N * DIM];
__device__ unsigned short g_lmax16[(size_t)Q_N * NBLK16];   // 16 MB, f16 bits
__device__ float g_ms[Q_N];
__device__ float g_comb[Q_N];

// ---- helpers ----
__device__ __forceinline__ uint32_t smem_u32(const void* p) {
    uint32_t a;
    asm("{ .reg .u64 t; cvta.to.shared.u64 t, %1; cvt.u32.u64 %0, t; }" : "=r"(a) : "l"(p));
    return a;
}
__device__ __forceinline__ void cpa16(void* s, const void* g) {
    unsigned sa = smem_u32(s);
    asm volatile("cp.async.cg.shared.global [%0], [%1], 16;" :: "r"(sa), "l"(g));
}
#define CP_COMMIT() asm volatile("cp.async.commit_group;" ::: "memory")
#define CP_WAIT0()  asm volatile("cp.async.wait_group 0;" ::: "memory")

__device__ __forceinline__ void load_tile(__half* dst, const __half* gsrc, int tid) {
#pragma unroll
    for (int t = 0; t < 8; t++) {
        int chunk = tid + t * 256;
        int row = chunk >> 4;
        int c   = chunk & 15;
        cpa16(dst + row * LDSK + c * 8, gsrc + row * DIM + c * 8);
    }
}
__device__ __forceinline__ void ldm_x4(uint32_t* r, uint32_t addr) {
    asm volatile("ldmatrix.sync.aligned.m8n8.x4.shared.b16 {%0,%1,%2,%3}, [%4];"
        : "=r"(r[0]), "=r"(r[1]), "=r"(r[2]), "=r"(r[3]) : "r"(addr));
}
// f16 x f16 -> f16 accum mma
__device__ __forceinline__ void mma_f16(uint32_t* c, const uint32_t* a, uint32_t b0, uint32_t b1) {
    asm volatile(
        "mma.sync.aligned.m16n8k16.row.col.f16.f16.f16.f16 "
        "{%0,%1}, {%2,%3,%4,%5}, {%6,%7}, {%0,%1};\n"
        : "+r"(c[0]), "+r"(c[1])
        : "r"(a[0]), "r"(a[1]), "r"(a[2]), "r"(a[3]), "r"(b0), "r"(b1));
}
__device__ __forceinline__ float bits_f16(unsigned short u) {
    __half h = *reinterpret_cast<__half*>(&u);
    return __half2float(h);
}

// =====================================================================
// Pass 0: fp32 -> fp16
// =====================================================================
__global__ void convert_kernel(const float4* __restrict__ qe, const float4* __restrict__ de) {
    const int i = blockIdx.x * blockDim.x + threadIdx.x;   // 0 .. D_N*DIM/8-1
#pragma unroll
    for (int r = 0; r < 2; r++) {
        int j = i + r * (D_N * DIM / 8);
        float4 v = de[j];
        ((__half2*)g_dh)[2 * j]     = __floats2half2_rn(v.x, v.y);
        ((__half2*)g_dh)[2 * j + 1] = __floats2half2_rn(v.z, v.w);
    }
    if (i < Q_N * DIM / 4) {
        float4 v = qe[i];
        ((__half2*)g_qh)[2 * i]     = __floats2half2_rn(v.x, v.y);
        ((__half2*)g_qh)[2 * i + 1] = __floats2half2_rn(v.z, v.w);
    }
}

// =====================================================================
// Pass 1: f16 GEMM (f16 accum), A register-resident, B-only smem traffic,
//         per-(row, 16-col block) f16 max table   [identical to R8/R11]
// =====================================================================
__global__ __launch_bounds__(256, 2) void approx_kernel() {
    extern __shared__ __half sm[];
    __half* As    = sm;                 // [128 x LDSK]
    __half* Bbase = As + TILE_E;        // 2 x [128 x LDSK]

    const int tid  = threadIdx.x;
    const int wid  = tid >> 5;
    const int lane = tid & 31;
    const int g    = lane >> 2;
    const int qr   = lane & 3;
    const int wid_m = wid >> 1;
    const int wid_n = wid & 1;
    const int qtile = blockIdx.x;
    const int d0    = blockIdx.y * (SUBS * TN);

    load_tile(As, g_qh + (size_t)qtile * TQ * DIM, tid);
    load_tile(Bbase, g_dh + (size_t)d0 * DIM, tid);
    CP_COMMIT();

    const int rowA  = wid_m * 32 + (lane & 15);
    const int colAb = ((lane >> 4) & 1) * 16;
    const uint32_t aBase = smem_u32(As) + rowA * ROWB + colAb;
    const int rowB  = wid_n * 64 + (lane & 7) + ((lane >> 4) << 3);
    const int colBb = ((lane >> 3) & 1) * 16;
    const uint32_t b_lane_off = (uint32_t)(rowB * ROWB + colBb);
    const uint32_t b_smem0 = smem_u32(Bbase);

    const int row0 = qtile * TQ + wid_m * 32 + g;

    CP_WAIT0();
    __syncthreads();

    uint32_t aF[2][8][4];
#pragma unroll
    for (int ks = 0; ks < 8; ks++) {
        ldm_x4(aF[0][ks], aBase + (uint32_t)(ks * 32));
        ldm_x4(aF[1][ks], aBase + 16 * ROWB + (uint32_t)(ks * 32));
    }

    for (int s = 0; s < SUBS; s++) {
        if (s > 0) { CP_WAIT0(); __syncthreads(); }
        if (s + 1 < SUBS) {
            load_tile(Bbase + ((s + 1) & 1) * TILE_E, g_dh + (size_t)(d0 + (s + 1) * TN) * DIM, tid);
            CP_COMMIT();
        }
        const uint32_t bH_base = b_smem0 + (uint32_t)(s & 1) * (TILE_E * 2) + b_lane_off;

        uint32_t acc[2][8][2];
#pragma unroll
        for (int mt = 0; mt < 2; mt++)
#pragma unroll
            for (int nt = 0; nt < 8; nt++) { acc[mt][nt][0] = 0u; acc[mt][nt][1] = 0u; }

#pragma unroll
        for (int ks = 0; ks < 8; ks++) {
            const uint32_t ko = (uint32_t)(ks * 32);
            uint32_t bH[4][4];
#pragma unroll
            for (int p = 0; p < 4; p++)
                ldm_x4(bH[p], bH_base + (uint32_t)(p * 16 * ROWB) + ko);
#pragma unroll
            for (int mt = 0; mt < 2; mt++)
#pragma unroll
                for (int p = 0; p < 4; p++) {
                    mma_f16(acc[mt][2 * p],     aF[mt][ks], bH[p][0], bH[p][1]);
                    mma_f16(acc[mt][2 * p + 1], aF[mt][ks], bH[p][2], bH[p][3]);
                }
        }

        const int gblk = (blockIdx.y * SUBS + s) * 8 + wid_n * 4;
#pragma unroll
        for (int sl = 0; sl < 4; sl++) {
            const int mt = sl >> 1, rg = sl & 1;
            unsigned short outv[4];
#pragma unroll
            for (int b = 0; b < 4; b++) {
                __half2 h0 = *reinterpret_cast<const __half2*>(&acc[mt][2 * b][rg]);
                __half2 h1 = *reinterpret_cast<const __half2*>(&acc[mt][2 * b + 1][rg]);
                __half2 hm = __hmax2(h0, h1);
                float m = fmaxf(__half2float(__low2half(hm)), __half2float(__high2half(hm)));
#pragma unroll
                for (int off = 1; off < 4; off <<= 1)
                    m = fmaxf(m, __shfl_xor_sync(0xffffffffu, m, off));
                __half hv = __float2half_rn(m);
                outv[b] = *reinterpret_cast<unsigned short*>(&hv);
            }
            if (qr == 0) {
                ushort4 v; v.x = outv[0]; v.y = outv[1]; v.z = outv[2]; v.w = outv[3];
                *(ushort4*)(g_lmax16 + (size_t)(row0 + sl * 8) * NBLK16 + gblk) = v;
            }
        }
    }
}

// =====================================================================
// Pass 2: FUSED scan + exact + weight gather. One block per query row.
// =====================================================================
__global__ void __launch_bounds__(256) scanexact_kernel(const float* __restrict__ qe,
                                                        const float* __restrict__ de,
                                                        const int* __restrict__ qids,
                                                        const int* __restrict__ dids,
                                                        const float* __restrict__ qwt,
                                                        const float* __restrict__ dwt) {
    const int row = blockIdx.x;
    const int t   = threadIdx.x;
    const int wid  = t >> 5;
    const int lane = t & 31;
    const bool hi  = (lane >= 16);
    __shared__ float red[256];
    __shared__ int lcnt;
    __shared__ uint32_t lblk[CAND_CAP];
    __shared__ float    cval[CAND_CAP];
    __shared__ unsigned ccol[CAND_CAP];

    // --- scan phase ---
    uint4 raw = ((const uint4*)(g_lmax16 + (size_t)row * NBLK16))[t];
    float v[8];
    v[0] = bits_f16((unsigned short)(raw.x & 0xFFFF));
    v[1] = bits_f16((unsigned short)(raw.x >> 16));
    v[2] = bits_f16((unsigned short)(raw.y & 0xFFFF));
    v[3] = bits_f16((unsigned short)(raw.y >> 16));
    v[4] = bits_f16((unsigned short)(raw.z & 0xFFFF));
    v[5] = bits_f16((unsigned short)(raw.z >> 16));
    v[6] = bits_f16((unsigned short)(raw.w & 0xFFFF));
    v[7] = bits_f16((unsigned short)(raw.w >> 16));

    float m = v[0];
#pragma unroll
    for (int j = 1; j < 8; j++) m = fmaxf(m, v[j]);
    red[t] = m;
    if (t == 0) lcnt = 0;
    __syncthreads();
    for (int off = 128; off > 0; off >>= 1) {
        if (t < off) red[t] = fmaxf(red[t], red[t + off]);
        __syncthreads();
    }
    const float thr = red[0] - MARGIN;

#pragma unroll
    for (int j = 0; j < 8; j++) {
        if (v[j] >= thr) {
            int p = atomicAdd(&lcnt, 1);
            if (p < CAND_CAP) lblk[p] = (uint32_t)(t * 8 + j);
        }
    }
    __syncthreads();
    const int cnt = lcnt < CAND_CAP ? lcnt : CAND_CAP;

    // --- exact phase: warp e-strided over candidates ---
    const float4 q4 = ((const float4*)(qe + (size_t)row * DIM))[lane];

    for (int e = wid; e < cnt; e += 8) {
        const int col0 = (int)lblk[e] * 16;

        float p[16];
#pragma unroll
        for (int b = 0; b < 2; b++) {
            float4 d[8];
#pragma unroll
            for (int r = 0; r < 8; r++)
                d[r] = ((const float4*)(de + (size_t)(col0 + b * 8 + r) * DIM))[lane];
#pragma unroll
            for (int r = 0; r < 8; r++)
                p[b * 8 + r] = fmaf(q4.x, d[r].x, fmaf(q4.y, d[r].y, fmaf(q4.z, d[r].z, q4.w * d[r].w)));
        }

        float y[8];
#pragma unroll
        for (int j = 0; j < 8; j++) {
            float a = hi ? p[j + 8] : p[j];
            float b = hi ? p[j] : p[j + 8];
            y[j] = a + __shfl_xor_sync(0xffffffffu, b, 16);
        }
#pragma unroll
        for (int off = 1; off < 16; off <<= 1)
#pragma unroll
            for (int j = 0; j < 8; j++)
                y[j] += __shfl_xor_sync(0xffffffffu, y[j], off);

        float    s = y[0];
        unsigned c = (unsigned)(col0 + (hi ? 8 : 0));
#pragma unroll
        for (int j = 1; j < 8; j++)
            if (y[j] > s) { s = y[j]; c = (unsigned)(col0 + (hi ? 8 : 0) + j); }
        {
            float    os = __shfl_xor_sync(0xffffffffu, s, 16);
            unsigned oc = __shfl_xor_sync(0xffffffffu, c, 16);
            if (os > s || (os == s && oc < c)) { s = os; c = oc; }
        }
        if (lane == 0) { cval[e] = s; ccol[e] = c; }
    }
    __syncthreads();

    // --- final reduce over candidates (warp 0); ties -> smaller column ---
    if (t < 32) {
        float    s = -3.402823466e38f;
        unsigned c = 0xFFFFFFFFu;
        for (int e = lane; e < cnt; e += 32) {
            float    es = cval[e];
            unsigned ec = ccol[e];
            if (es > s || (es == s && ec < c)) { s = es; c = ec; }
        }
#pragma unroll
        for (int off = 1; off < 32; off <<= 1) {
            float    os = __shfl_xor_sync(0xffffffffu, s, off);
            unsigned oc = __shfl_xor_sync(0xffffffffu, c, off);
            if (os > s || (os == s && oc < c)) { s = os; c = oc; }
        }
        if (lane == 0) {
            g_ms[row]   = s;
            g_comb[row] = qwt[qids[row]] * dwt[dids[(int)c]];   // gather here, spread over 4096 blocks
        }
    }
}

// =====================================================================
// Pass 3: coalesced reduction over g_ms/g_comb -> final scalar
// =====================================================================
__global__ void finalize_kernel(float* __restrict__ out) {
    __shared__ float sA[256], sB[256], sC[256];
    int tid = threadIdx.x;
    float a = 0.f, b = 0.f, c = 0.f;
#pragma unroll
    for (int j = 0; j < Q_N / 1024; j++) {               // float4 strides: 4096/4/256 = 4
        float4 cm = ((const float4*)g_comb)[tid + j * 256];
        float4 ms = ((const float4*)g_ms)[tid + j * 256];
        a += (cm.x + cm.y) + (cm.z + cm.w);
        b += fmaf(cm.x, ms.x, fmaf(cm.y, ms.y, fmaf(cm.z, ms.z, cm.w * ms.w)));
        c += (ms.x + ms.y) + (ms.z + ms.w);
    }
    sA[tid] = a; sB[tid] = b; sC[tid] = c;
    __syncthreads();
    for (int off = 128; off > 0; off >>= 1) {
        if (tid < off) { sA[tid] += sA[tid + off]; sB[tid] += sB[tid + off]; sC[tid] += sC[tid + off]; }
        __syncthreads();
    }
    if (tid == 0) out[0] = (sA[0] > 0.f) ? (sB[0] / sA[0]) : (sC[0] / (float)Q_N);
}

// =====================================================================
// launch
// =====================================================================
extern "C" void kernel_launch(void* const* d_in, const int* in_sizes, int n_in,
                              void* d_out, int out_size) {
    const float* qe  = (const float*)d_in[0];
    const float* de  = (const float*)d_in[1];
    const int*   qid = (const int*)d_in[2];
    const int*   did = (const int*)d_in[3];
    const float* qwt = (const float*)d_in[4];
    const float* dwt = (const float*)d_in[5];
    float* out = (float*)d_out;

    size_t smem = (size_t)(3 * TILE_E) * sizeof(__half);   // 104,448 B -> 2 CTAs/SM
    cudaFuncSetAttribute(approx_kernel, cudaFuncAttributeMaxDynamicSharedMemorySize, (int)smem);

    convert_kernel<<<D_N * DIM / 8 / 256, 256>>>((const float4*)qe, (const float4*)de);
    approx_kernel<<<dim3(Q_N / TQ, NSLICE), 256, smem>>>();
    scanexact_kernel<<<Q_N, 256>>>(qe, de, qid, did, qwt, dwt);
    finalize_kernel<<<1, 256>>>(out);
}